// round 16
// baseline (speedup 1.0000x reference)
#include <cuda_runtime.h>
#include <cuda_bf16.h>
#include <math.h>
#include <stdint.h>

#define Nn 4096
#define Pp 32768
#define Ee 768
#define Cc 256
#define Hh 4
#define Dd 64
#define Ll 256
#define Mm 8
#define MLPH 1024
#define NE (2*Pp)
#define DEG_CAP 96

#define KC_E 12
#define KC_C 4

// ---------------- scratch ----------------
__device__ float g_A[Nn*MLPH];
__device__ float g_B[Nn*MLPH];
__device__ float g_U[Nn*MLPH];
__device__ float g_V[Nn*MLPH];
__device__ float g_h[Nn*Cc];
__device__ float g_sis[Nn*Hh], g_sid[Nn*Hh], g_ses[Nn*Hh], g_sed[Nn*Hh];
__device__ unsigned char g_m1[Pp], g_m2[Pp];
__device__ float g_loss[Pp];
__device__ int g_cnt[Nn];          // zero at t=0; re-zeroed at end of each graph exec
__device__ int g_esrc[Nn*DEG_CAP];
__device__ unsigned int g_emeta[Nn*DEG_CAP];

// bf16 pre-swizzled panels (tile = 128 rows x 64 bf16 = 16KB)
__device__ __nv_bfloat16 g_PE  [(size_t)32*(2*KC_E)*8192];
__device__ __nv_bfloat16 g_PX  [(size_t)32*(2*KC_C)*8192];
__device__ __nv_bfloat16 g_Wbig [(size_t)18*(2*KC_E)*8192];
__device__ __nv_bfloat16 g_Wloop[(size_t)10*(2*KC_C)*8192];

__device__ __forceinline__ float warp_sum(float v){
#pragma unroll
    for(int o=16;o;o>>=1) v+=__shfl_xor_sync(0xffffffffu,v,o);
    return v;
}

// ---------------- PTX helpers ----------------
__device__ __forceinline__ uint32_t smem_to_u32(const void* p){
    uint32_t a;
    asm("{ .reg .u64 t; cvta.to.shared.u64 t, %1; cvt.u32.u64 %0, t; }" : "=r"(a) : "l"(p));
    return a;
}
__device__ __forceinline__ void ldmx4(uint32_t &r0,uint32_t &r1,uint32_t &r2,uint32_t &r3,uint32_t addr){
    asm volatile("ldmatrix.sync.aligned.m8n8.x4.shared.b16 {%0,%1,%2,%3}, [%4];"
        : "=r"(r0),"=r"(r1),"=r"(r2),"=r"(r3) : "r"(addr));
}
__device__ __forceinline__ void mma16816(float* c, const uint32_t* a, uint32_t b0, uint32_t b1){
    asm volatile("mma.sync.aligned.m16n8k16.row.col.f32.bf16.bf16.f32 "
        "{%0,%1,%2,%3}, {%4,%5,%6,%7}, {%8,%9}, {%0,%1,%2,%3};"
        : "+f"(c[0]),"+f"(c[1]),"+f"(c[2]),"+f"(c[3])
        : "r"(a[0]),"r"(a[1]),"r"(a[2]),"r"(a[3]),"r"(b0),"r"(b1));
}
#define CP_ASYNC16(dst,src) \
    asm volatile("cp.async.cg.shared.global [%0], [%1], 16;" :: "r"(dst),"l"(src))
#define CP_COMMIT asm volatile("cp.async.commit_group;" ::: "memory")
#define CP_WAIT2  asm volatile("cp.async.wait_group 2;" ::: "memory")
#define CP_WAIT1  asm volatile("cp.async.wait_group 1;" ::: "memory")
#define CP_WAIT0  asm volatile("cp.async.wait_group 0;" ::: "memory")

__device__ __forceinline__ uint32_t sw128(uint32_t off){ return off ^ ((off>>3)&0x70u); }

__device__ __forceinline__ void panel_write(__nv_bfloat16* pan, int panKc, int mglob, int cglob, float v){
    int pm = mglob>>7, prow = mglob&127, chunk = cglob>>6, col = cglob&63;
    uint32_t off = sw128((uint32_t)(prow*128 + col*2));
    char* hi = (char*)(pan + ((size_t)pm*(2*panKc)+chunk)*8192);
    char* lo = (char*)(pan + ((size_t)pm*(2*panKc)+panKc+chunk)*8192);
    __nv_bfloat16 h = __float2bfloat16(v);
    *(__nv_bfloat16*)(hi+off) = h;
    *(__nv_bfloat16*)(lo+off) = __float2bfloat16(v - __bfloat162float(h));
}

__device__ __forceinline__ void w_write(const float* __restrict__ W, __nv_bfloat16* P,
                                        int N, int KcN, int idx){
    int k = idx / N, n = idx - k*N;
    float v = W[idx];
    __nv_bfloat16 hi = __float2bfloat16(v);
    __nv_bfloat16 lo = __float2bfloat16(v - __bfloat162float(hi));
    int nblk = n>>7, row = n&127, chunk = k>>6, col = k&63;
    uint32_t off = sw128((uint32_t)(row*128 + col*2));
    char* baseHi = (char*)(P + ((size_t)nblk*(2*KcN)+chunk)*8192);
    char* baseLo = (char*)(P + ((size_t)nblk*(2*KcN)+KcN+chunk)*8192);
    *(__nv_bfloat16*)(baseHi + off) = hi;
    *(__nv_bfloat16*)(baseLo + off) = lo;
}

// ---------------- mega prologue: eemb | edge scatter | weight panels ----------------
__global__ void prologue_kernel(const float* __restrict__ sent_emb,
                                const int* __restrict__ ev_sent,
                                const int* __restrict__ ev_start,
                                const int* __restrict__ ev_end,
                                const int* __restrict__ pair_idx,
                                const int* __restrict__ rel_type,
                                const float* __restrict__ Win,
                                const float* __restrict__ W1,
                                const float* __restrict__ Wp){
    int b = blockIdx.x, tid = threadIdx.x;
    if(b < Nn){
        int n = b;
        int s = ev_sent[n], st = ev_start[n], en = ev_end[n];
        float inv = 1.0f/(float)(en-st);
        const float* base = sent_emb + (size_t)s*Ll*Ee;
        if(tid < Ee/4){
            float4 acc = make_float4(0.f,0.f,0.f,0.f);
#pragma unroll
            for(int m=0;m<Mm;m++){
                int pos = st+m;
                if(pos<en){
                    int pc = pos<Ll-1?pos:Ll-1;
                    float4 t = *(const float4*)(base + (size_t)pc*Ee + tid*4);
                    acc.x += t.x; acc.y += t.y; acc.z += t.z; acc.w += t.w;
                }
            }
            int c = tid*4;
            panel_write(g_PE, KC_E, n, c+0, acc.x*inv);
            panel_write(g_PE, KC_E, n, c+1, acc.y*inv);
            panel_write(g_PE, KC_E, n, c+2, acc.z*inv);
            panel_write(g_PE, KC_E, n, c+3, acc.w*inv);
        }
    } else if(b < Nn + NE/256){
        int e = (b - Nn)*256 + tid;
        int p = e & (Pp-1);
        int half = (e>=Pp);
        int src = half ? pair_idx[2*p+1] : pair_idx[2*p];
        int dst = half ? pair_idx[2*p]   : pair_idx[2*p+1];
        unsigned int intra = (rel_type[p]==0) ? 0x40000000u : 0u;
        int slot = atomicAdd(&g_cnt[dst],1);
        int idx = dst*DEG_CAP + slot;
        g_esrc[idx] = src;
        g_emeta[idx] = (unsigned int)p | (half ? 0x80000000u : 0u) | intra;
    } else {
        int wb = b - (Nn + NE/256);   // 0..8191
        if(wb < 768){
            w_write(Win, g_Wbig, Cc, KC_E, wb*256+tid);
        } else if(wb < 3840){
            w_write(W1, g_Wbig + (size_t)2*(2*KC_E)*8192, MLPH, KC_E, (wb-768)*256+tid);
        } else if(wb < 6912){
            w_write(W1 + (size_t)Ee*MLPH, g_Wbig + (size_t)10*(2*KC_E)*8192, MLPH, KC_E, (wb-3840)*256+tid);
        } else if(wb < 7936){
            w_write(W1 + (size_t)2*Ee*MLPH, g_Wloop, MLPH, KC_C, (wb-6912)*256+tid);
        } else {
            w_write(Wp, g_Wloop + (size_t)8*(2*KC_C)*8192, Cc, KC_C, (wb-7936)*256+tid);
        }
    }
}

// ---------------- epilogue descriptor ----------------
struct Epi {
    int type;              // 0 fp32 out(+bias); 1 UV; 2 panel out(+bias)
    float* out;
    const float* bias;
    int N;
    float* out2;
    __nv_bfloat16* pan;
    int panKc;
};

// ---------------- fused GEMM: 128x128 CTA tile, 3-stage ----------------
#define STAGE_BYTES 32768
#define GEMM_SMEM   (3*STAGE_BYTES)

__global__ void __launch_bounds__(256,2)
gemm_fused(const __nv_bfloat16* __restrict__ Apan,
           const __nv_bfloat16* __restrict__ Bpan,
           int KcN, int s1, int s2,
           Epi e0, Epi e1, Epi e2,
           const float* __restrict__ addA,
           const float* __restrict__ addB)
{
    extern __shared__ __align__(128) char smem[];
    const uint32_t sb = smem_to_u32(smem);
    const int tid = threadIdx.x;
    const int wid = tid >> 5;
    const int lane = tid & 31;
    const int mblk = blockIdx.y, nblk = blockIdx.x;
    const int wm = wid & 3;
    const int wn = wid >> 2;
    const int nc = 3*KcN;

    float acc[2][8][4];
#pragma unroll
    for(int i=0;i<2;i++)
#pragma unroll
        for(int j=0;j<8;j++)
#pragma unroll
            for(int q=0;q<4;q++) acc[i][j][q]=0.f;

    const int arow = wm*32 + (lane & 15);
    const int acol = ((lane >> 4) & 1) * 8;
    const int bnof = ((lane >> 4) & 1) * 8 + (lane & 7);
    const int bkof = ((lane >> 3) & 1) * 8;

    auto issue_chunk = [&](int c, uint32_t dst){
        int seg = (c >= 2*KcN) ? 2 : ((c >= KcN) ? 1 : 0);
        int within = c - seg*KcN;
        int aC = (seg==1 ? KcN : 0) + within;
        int bC = (seg==2 ? KcN : 0) + within;
        const uint4* Ag = (const uint4*)(Apan + ((size_t)mblk*(2*KcN)+aC)*8192);
        const uint4* Bg = (const uint4*)(Bpan + ((size_t)nblk*(2*KcN)+bC)*8192);
#pragma unroll
        for(int i=0;i<4;i++){
            CP_ASYNC16(dst + (tid + i*256)*16, Ag + tid + i*256);
            CP_ASYNC16(dst + 16384 + (tid + i*256)*16, Bg + tid + i*256);
        }
        CP_COMMIT;
    };

    issue_chunk(0, sb);
    if(nc > 1) issue_chunk(1, sb + STAGE_BYTES);

    int bufc = 0;
    for(int c=0;c<nc;c++){
        if(c+2 < nc){
            int b2 = bufc+2; if(b2>=3) b2-=3;
            issue_chunk(c+2, sb + b2*STAGE_BYTES);
            CP_WAIT2;
        } else if(c+1 < nc){
            CP_WAIT1;
        } else {
            CP_WAIT0;
        }
        __syncthreads();

        uint32_t abase = sb + bufc*STAGE_BYTES;
        uint32_t bbase = abase + 16384;
#pragma unroll
        for(int ks=0;ks<4;ks++){
            uint32_t af[2][4];
#pragma unroll
            for(int mf=0;mf<2;mf++){
                uint32_t off = (uint32_t)((arow + mf*16)*128 + (ks*16 + acol)*2);
                ldmx4(af[mf][0],af[mf][1],af[mf][2],af[mf][3], abase + sw128(off));
            }
#pragma unroll
            for(int g=0;g<4;g++){
                uint32_t b0,b1,b2,b3;
                uint32_t off = (uint32_t)((wn*64 + g*16 + bnof)*128 + (ks*16 + bkof)*2);
                ldmx4(b0,b1,b2,b3, bbase + sw128(off));
#pragma unroll
                for(int mf=0;mf<2;mf++){
                    mma16816(acc[mf][2*g+0], af[mf], b0, b1);
                    mma16816(acc[mf][2*g+1], af[mf], b2, b3);
                }
            }
        }
        __syncthreads();
        if(++bufc==3) bufc=0;
    }

    Epi E; int regStart;
    if(nblk < s1){ E = e0; regStart = 0; }
    else if(nblk < s2){ E = e1; regStart = s1; }
    else { E = e2; regStart = s2; }

    int rbase = mblk*128 + wm*32 + (lane>>2);
    int cbase = (nblk - regStart)*128 + wn*64 + (lane&3)*2;

#pragma unroll
    for(int mf=0;mf<2;mf++){
#pragma unroll
        for(int nf=0;nf<8;nf++){
            int r  = rbase + mf*16;
            int cc = cbase + nf*8;
            float g0=acc[mf][nf][0], g1=acc[mf][nf][1];
            float g2=acc[mf][nf][2], g3=acc[mf][nf][3];
            if(E.type==0){
                float b0 = E.bias ? E.bias[cc]   : 0.f;
                float b1 = E.bias ? E.bias[cc+1] : 0.f;
                size_t i0 = (size_t)r*E.N + cc;
                size_t i1 = (size_t)(r+8)*E.N + cc;
                *(float2*)(E.out + i0) = make_float2(g0+b0, g1+b1);
                *(float2*)(E.out + i1) = make_float2(g2+b0, g3+b1);
            } else if(E.type==1){
                float b0 = E.bias[cc], b1 = E.bias[cc+1];
                size_t i0 = (size_t)r*E.N + cc;
                size_t i1 = (size_t)(r+8)*E.N + cc;
                float2 a0 = *(const float2*)(addA + i0);
                float2 a1 = *(const float2*)(addA + i1);
                float2 v0 = *(const float2*)(addB + i0);
                float2 v1 = *(const float2*)(addB + i1);
                *(float2*)(E.out  + i0) = make_float2(a0.x+g0+b0, a0.y+g1+b1);
                *(float2*)(E.out  + i1) = make_float2(a1.x+g2+b0, a1.y+g3+b1);
                *(float2*)(E.out2 + i0) = make_float2(v0.x-g0, v0.y-g1);
                *(float2*)(E.out2 + i1) = make_float2(v1.x-g2, v1.y-g3);
            } else {
                float b0 = E.bias ? E.bias[cc]   : 0.f;
                float b1 = E.bias ? E.bias[cc+1] : 0.f;
                panel_write(E.pan, E.panKc, r,   cc,   g0+b0);
                panel_write(E.pan, E.panKc, r,   cc+1, g1+b1);
                panel_write(E.pan, E.panKc, r+8, cc,   g2+b0);
                panel_write(E.pan, E.panKc, r+8, cc+1, g3+b1);
            }
        }
    }
}

// ---------------- pair MLP (4 pairs/warp interleaved ILP) + s-scores ----------------
__global__ void pair_s_kernel(const int* __restrict__ pair_idx,
                              const float* __restrict__ W2, const float* __restrict__ b2,
                              const int* __restrict__ target,
                              float w_it, int accum, float* __restrict__ pred_out,
                              const float* __restrict__ asi, const float* __restrict__ adi,
                              const float* __restrict__ ase, const float* __restrict__ ade)
{
    int tid = threadIdx.x; // 256
    if(blockIdx.x < Pp/32){
        __shared__ __align__(16) float W2t[3][MLPH];
        __shared__ float b2s[3];
        for(int i=tid;i<3072;i+=256){
            float v = W2[i];
            W2t[i%3][i/3] = v;
        }
        if(tid<3) b2s[tid]=b2[tid];
        __syncthreads();
        int lane = tid & 31;
        int pbase = blockIdx.x*32 + (tid>>5)*4;
        const float4* ur[4];
        const float4* vr[4];
#pragma unroll
        for(int q=0;q<4;q++){
            int p0 = pair_idx[2*(pbase+q)], p1 = pair_idx[2*(pbase+q)+1];
            ur[q] = (const float4*)(g_U + (size_t)p0*MLPH);
            vr[q] = (const float4*)(g_V + (size_t)p1*MLPH);
        }
        const float4* w0t = (const float4*)W2t[0];
        const float4* w1t = (const float4*)W2t[1];
        const float4* w2t = (const float4*)W2t[2];
        float a0[4]={0,0,0,0}, a1[4]={0,0,0,0}, a2[4]={0,0,0,0};
#pragma unroll
        for(int k=0;k<8;k++){
            int j4 = lane + k*32;
            float4 w0 = w0t[j4], w1 = w1t[j4], w2 = w2t[j4];
#pragma unroll
            for(int q=0;q<4;q++){
                float4 u = ur[q][j4];
                float4 v = vr[q][j4];
                float h0 = fmaxf(u.x+v.x,0.f);
                float h1 = fmaxf(u.y+v.y,0.f);
                float h2 = fmaxf(u.z+v.z,0.f);
                float h3 = fmaxf(u.w+v.w,0.f);
                a0[q] += h0*w0.x + h1*w0.y + h2*w0.z + h3*w0.w;
                a1[q] += h0*w1.x + h1*w1.y + h2*w1.z + h3*w1.w;
                a2[q] += h0*w2.x + h1*w2.y + h2*w2.z + h3*w2.w;
            }
        }
#pragma unroll
        for(int q=0;q<4;q++){
            a0[q]=warp_sum(a0[q]); a1[q]=warp_sum(a1[q]); a2[q]=warp_sum(a2[q]);
        }
        if(lane==0){
#pragma unroll
            for(int q=0;q<4;q++){
                int p = pbase + q;
                float r0 = a0[q]+b2s[0];
                float r1 = a1[q]+b2s[1];
                float r2 = a2[q]+b2s[2];
                float mv=r0; int arg=0;
                if(r1>mv){mv=r1;arg=1;}
                if(r2>mv){mv=r2;arg=2;}
                float e0=expf(r0-mv), e1=expf(r1-mv), e2=expf(r2-mv);
                float ssum=e0+e1+e2;
                int conf = (1.0f/ssum) > 0.5f;
                g_m1[p] = (unsigned char)(conf && (arg==1));
                g_m2[p] = (unsigned char)(conf && (arg==2));
                int t = target[p];
                float lse = mv + logf(ssum);
                float pr = (t==0)?r0:((t==1)?r1:r2);
                float prev = accum ? g_loss[p] : 0.f;
                g_loss[p] = prev + w_it*(lse - pr);
                if(pred_out){
                    pred_out[3*p+0]=r0; pred_out[3*p+1]=r1; pred_out[3*p+2]=r2;
                }
            }
        }
    } else {
        int n = (blockIdx.x - Pp/32)*2 + (tid>>7);
        int w = (tid>>5)&3, lane = tid&31;
        const float* hr = g_h + (size_t)n*Cc + w*Dd;
        float h0 = hr[lane], h1 = hr[32+lane];
        float v0 = h0*asi[w*Dd+lane] + h1*asi[w*Dd+32+lane];
        float v1 = h0*adi[w*Dd+lane] + h1*adi[w*Dd+32+lane];
        float v2 = h0*ase[w*Dd+lane] + h1*ase[w*Dd+32+lane];
        float v3 = h0*ade[w*Dd+lane] + h1*ade[w*Dd+32+lane];
        v0=warp_sum(v0); v1=warp_sum(v1); v2=warp_sum(v2); v3=warp_sum(v3);
        if(lane==0){
            g_sis[n*Hh+w]=v0; g_sid[n*Hh+w]=v1;
            g_ses[n*Hh+w]=v2; g_sed[n*Hh+w]=v3;
        }
    }
}

// ---------------- loss reduce + g_cnt re-zero ----------------
__global__ void loss_reduce(float* __restrict__ out){
    int tid = threadIdx.x;
    if(blockIdx.x == 0){
        __shared__ float sh[256];
        float s=0.f;
        for(int i=tid;i<Pp;i+=256) s+=g_loss[i];
        sh[tid]=s; __syncthreads();
        for(int o=128;o;o>>=1){
            if(tid<o) sh[tid]+=sh[tid+o];
            __syncthreads();
        }
        if(tid==0) out[0]=sh[0]/(float)Pp;
    } else {
        g_cnt[(blockIdx.x-1)*256 + tid] = 0;
    }
}

// ---------------- fused GAT attention (bucket CSR), writes x panels ----------------
__global__ void attn_kernel(){
    int n = blockIdx.x;
    int tid = threadIdx.x; // 256
    int hh = tid>>6;
    __shared__ int ssrc[64];
    __shared__ unsigned int smeta[64];
    __shared__ float exI[64][4];
    __shared__ float exE[64][4];
    __shared__ float shmaxI[4], shmaxE[4], shdenI[4], shdenE[4];
    __shared__ float wred[8][8];

    float sdI[4], sdE[4], aself[4];
#pragma unroll
    for(int h=0;h<4;h++){
        sdI[h]=g_sid[n*4+h];
        sdE[h]=g_sed[n*4+h];
        float a = g_sis[n*4+h]+sdI[h];
        aself[h] = (a>=0.f)? a : 0.2f*a;
    }

    int beg = n*DEG_CAP;
    int end = beg + g_cnt[n];

    float mI[4], mE[4];
#pragma unroll
    for(int h=0;h<4;h++){ mI[h]=fmaxf(-1e9f,aself[h]); mE[h]=-1e9f; }
    for(int e=beg+tid;e<end;e+=256){
        int src = g_esrc[e];
        unsigned int meta = g_emeta[e];
        unsigned int p = meta & 0x0FFFFFFFu;
        bool mm = (meta & 0x80000000u) ? (g_m2[p]!=0) : (g_m1[p]!=0);
        if(!mm) continue;
        if(meta & 0x40000000u){
#pragma unroll
            for(int h=0;h<4;h++){
                float a = g_sis[src*4+h]+sdI[h];
                a = (a>=0.f)? a : 0.2f*a;
                mI[h]=fmaxf(mI[h],a);
            }
        } else {
#pragma unroll
            for(int h=0;h<4;h++){
                float a = g_ses[src*4+h]+sdE[h];
                a = (a>=0.f)? a : 0.2f*a;
                mE[h]=fmaxf(mE[h],a);
            }
        }
    }
#pragma unroll
    for(int o=16;o;o>>=1){
#pragma unroll
        for(int h=0;h<4;h++){
            mI[h]=fmaxf(mI[h],__shfl_xor_sync(0xffffffffu,mI[h],o));
            mE[h]=fmaxf(mE[h],__shfl_xor_sync(0xffffffffu,mE[h],o));
        }
    }
    int wid = tid>>5, lane = tid&31;
    if(lane==0){
#pragma unroll
        for(int h=0;h<4;h++){ wred[wid][h]=mI[h]; wred[wid][4+h]=mE[h]; }
    }
    __syncthreads();
    if(tid<8){
        float m=-1e9f;
#pragma unroll
        for(int w=0;w<8;w++) m=fmaxf(m,wred[w][tid]);
        if(tid<4) shmaxI[tid]=m; else shmaxE[tid-4]=m;
    }
    __syncthreads();
    float mymaxI = shmaxI[hh];
    float mymaxE = shmaxE[hh];

    float accI=0.f, accE=0.f, dI=0.f, dE=0.f;
    for(int c0=beg;c0<end;c0+=64){
        int ne = min(64, end-c0);
        if(tid<ne){ ssrc[tid]=g_esrc[c0+tid]; smeta[tid]=g_emeta[c0+tid]; }
        __syncthreads();
        int i = tid & 63;
        if(i<ne){
            int src = ssrc[i];
            unsigned int meta = smeta[i];
            unsigned int p = meta & 0x0FFFFFFFu;
            bool mm = (meta & 0x80000000u) ? (g_m2[p]!=0) : (g_m1[p]!=0);
            float eI=0.f, eE=0.f;
            if(mm){
                if(meta & 0x40000000u){
                    float a = g_sis[src*4+hh]+sdI[hh];
                    a = (a>=0.f)? a : 0.2f*a;
                    eI = expf(a - mymaxI);
                } else {
                    float a = g_ses[src*4+hh]+sdE[hh];
                    a = (a>=0.f)? a : 0.2f*a;
                    eE = expf(a - mymaxE);
                }
            }
            exI[i][hh]=eI; exE[i][hh]=eE;
            dI += eI; dE += eE;
        }
        __syncthreads();
        for(int i2=0;i2<ne;i2++){
            float wI = exI[i2][hh];
            float wE = exE[i2][hh];
            if(wI!=0.f || wE!=0.f){
                float hv = g_h[(size_t)ssrc[i2]*Cc + tid];
                accI += wI*hv;
                accE += wE*hv;
            }
        }
        __syncthreads();
    }

    float rdI = warp_sum(dI), rdE = warp_sum(dE);
    if(lane==0){ wred[wid][0]=rdI; wred[wid][1]=rdE; }
    __syncthreads();
    if(tid<4){
        float selfe = expf(aself[tid]-shmaxI[tid]);
        shdenI[tid] = wred[2*tid][0]+wred[2*tid+1][0]+selfe;
        shdenE[tid] = wred[2*tid][1]+wred[2*tid+1][1];
    }
    __syncthreads();

    float selfe = expf(aself[hh]-mymaxI);
    accI += selfe * g_h[(size_t)n*Cc + tid];

    float outI = accI/(shdenI[hh]+1e-9f);
    float outE = accE/(shdenE[hh]+1e-9f);
    float val = 0.5f*outI + 0.5f*outE;
    panel_write(g_PX, KC_C, n, tid, val);
}

// ---------------- host launch ----------------
extern "C" void kernel_launch(void* const* d_in, const int* in_sizes, int n_in,
                              void* d_out, int out_size)
{
    const float* sent_emb  = (const float*)d_in[0];
    const float* proj_in_W = (const float*)d_in[1];
    const float* proj_in_b = (const float*)d_in[2];
    const float* proj_W    = (const float*)d_in[3];
    const float* proj_b    = (const float*)d_in[4];
    const float* asi       = (const float*)d_in[5];
    const float* adi       = (const float*)d_in[6];
    const float* ase       = (const float*)d_in[7];
    const float* ade       = (const float*)d_in[8];
    const float* mlp_W1    = (const float*)d_in[9];
    const float* mlp_b1    = (const float*)d_in[10];
    const float* mlp_W2    = (const float*)d_in[11];
    const float* mlp_b2    = (const float*)d_in[12];
    const int*   ev_sent   = (const int*)d_in[13];
    const int*   ev_start  = (const int*)d_in[14];
    const int*   ev_end    = (const int*)d_in[15];
    const int*   pair_idx  = (const int*)d_in[16];
    const int*   rel_type  = (const int*)d_in[17];
    const int*   target    = (const int*)d_in[18];
    float* out = (float*)d_out;

    static float *pA=nullptr,*pB=nullptr,*pU=nullptr,*pV=nullptr,*pH=nullptr;
    static __nv_bfloat16 *qE,*qX,*qWbig,*qWloop;
    if(!pA){
        cudaGetSymbolAddress((void**)&pA, g_A);
        cudaGetSymbolAddress((void**)&pB, g_B);
        cudaGetSymbolAddress((void**)&pU, g_U);
        cudaGetSymbolAddress((void**)&pV, g_V);
        cudaGetSymbolAddress((void**)&pH, g_h);
        cudaGetSymbolAddress((void**)&qE,    g_PE);
        cudaGetSymbolAddress((void**)&qX,    g_PX);
        cudaGetSymbolAddress((void**)&qWbig, g_Wbig);
        cudaGetSymbolAddress((void**)&qWloop,g_Wloop);
        cudaFuncSetAttribute(gemm_fused, cudaFuncAttributeMaxDynamicSharedMemorySize, GEMM_SMEM);
    }

    // single prologue launch: eemb | scatter | weight panels
    prologue_kernel<<<Nn + NE/256 + 8192, 256>>>(sent_emb, ev_sent, ev_start, ev_end,
                                                 pair_idx, rel_type,
                                                 proj_in_W, mlp_W1, proj_W);

    // fused big GEMM: [x-panels(2 tiles) | A(8) | B(8)] = e_emb @ [Win | W1a | W1b]
    {
        Epi ex;  ex.type=2;  ex.out=nullptr; ex.bias=proj_in_b; ex.N=0;    ex.out2=nullptr; ex.pan=qX; ex.panKc=KC_C;
        Epi ea;  ea.type=0;  ea.out=pA;      ea.bias=nullptr;   ea.N=MLPH; ea.out2=nullptr; ea.pan=nullptr; ea.panKc=0;
        Epi eb;  eb.type=0;  eb.out=pB;      eb.bias=nullptr;   eb.N=MLPH; eb.out2=nullptr; eb.pan=nullptr; eb.panKc=0;
        gemm_fused<<<dim3(18, Nn/128),256,GEMM_SMEM>>>(qE, qWbig, KC_E, 2, 10, ex, ea, eb, nullptr, nullptr);
    }

    for(int it=0; it<3; it++){
        Epi eu;  eu.type=1;  eu.out=pU;  eu.bias=mlp_b1; eu.N=MLPH; eu.out2=pV;      eu.pan=nullptr; eu.panKc=0;
        Epi eh;  eh.type=0;  eh.out=pH;  eh.bias=proj_b; eh.N=Cc;   eh.out2=nullptr; eh.pan=nullptr; eh.panKc=0;
        int gx = (it<2) ? 10 : 8;
        gemm_fused<<<dim3(gx, Nn/128),256,GEMM_SMEM>>>(qX, qWloop, KC_C, 8, 10, eu, eh, eh, pA, pB);

        int sgrid = (it<2) ? (Pp/32 + Nn/2) : (Pp/32);
        pair_s_kernel<<<sgrid,256>>>(pair_idx, mlp_W2, mlp_b2, target,
                                     1.0f/(float)(it+1), it>0,
                                     (it==2) ? (out+1) : nullptr,
                                     asi, adi, ase, ade);
        if(it<2){
            attn_kernel<<<Nn,256>>>();
        }
    }
    loss_reduce<<<1 + Nn/256,256>>>(out);
}

// round 17
// speedup vs baseline: 1.0366x; 1.0366x over previous
#include <cuda_runtime.h>
#include <cuda_bf16.h>
#include <math.h>
#include <stdint.h>

#define Nn 4096
#define Pp 32768
#define Ee 768
#define Cc 256
#define Hh 4
#define Dd 64
#define Ll 256
#define Mm 8
#define MLPH 1024
#define NE (2*Pp)
#define DEG_CAP 96

#define KC_E 12
#define KC_C 4

// ---------------- scratch ----------------
__device__ float g_A[Nn*MLPH];
__device__ float g_B[Nn*MLPH];
__device__ float g_U[Nn*MLPH];
__device__ float g_V[Nn*MLPH];
__device__ float g_h[Nn*Cc];
__device__ float g_sis[Nn*Hh], g_sid[Nn*Hh], g_ses[Nn*Hh], g_sed[Nn*Hh];
__device__ unsigned char g_m1[Pp], g_m2[Pp];
__device__ float g_loss[Pp];
__device__ int g_cnt[Nn];          // zero at t=0; re-zeroed at end of each graph exec
__device__ int g_esrc[Nn*DEG_CAP];
__device__ unsigned int g_emeta[Nn*DEG_CAP];

// bf16 pre-swizzled panels (tile = 128 rows x 64 bf16 = 16KB)
__device__ __nv_bfloat16 g_PE  [(size_t)32*(2*KC_E)*8192];
__device__ __nv_bfloat16 g_PX  [(size_t)32*(2*KC_C)*8192];
__device__ __nv_bfloat16 g_Wbig [(size_t)18*(2*KC_E)*8192];
__device__ __nv_bfloat16 g_Wloop[(size_t)10*(2*KC_C)*8192];

__device__ __forceinline__ float warp_sum(float v){
#pragma unroll
    for(int o=16;o;o>>=1) v+=__shfl_xor_sync(0xffffffffu,v,o);
    return v;
}

// ---------------- PTX helpers ----------------
__device__ __forceinline__ uint32_t smem_to_u32(const void* p){
    uint32_t a;
    asm("{ .reg .u64 t; cvta.to.shared.u64 t, %1; cvt.u32.u64 %0, t; }" : "=r"(a) : "l"(p));
    return a;
}
__device__ __forceinline__ void ldmx4(uint32_t &r0,uint32_t &r1,uint32_t &r2,uint32_t &r3,uint32_t addr){
    asm volatile("ldmatrix.sync.aligned.m8n8.x4.shared.b16 {%0,%1,%2,%3}, [%4];"
        : "=r"(r0),"=r"(r1),"=r"(r2),"=r"(r3) : "r"(addr));
}
__device__ __forceinline__ void mma16816(float* c, const uint32_t* a, uint32_t b0, uint32_t b1){
    asm volatile("mma.sync.aligned.m16n8k16.row.col.f32.bf16.bf16.f32 "
        "{%0,%1,%2,%3}, {%4,%5,%6,%7}, {%8,%9}, {%0,%1,%2,%3};"
        : "+f"(c[0]),"+f"(c[1]),"+f"(c[2]),"+f"(c[3])
        : "r"(a[0]),"r"(a[1]),"r"(a[2]),"r"(a[3]),"r"(b0),"r"(b1));
}
#define CP_ASYNC16(dst,src) \
    asm volatile("cp.async.cg.shared.global [%0], [%1], 16;" :: "r"(dst),"l"(src))
#define CP_COMMIT asm volatile("cp.async.commit_group;" ::: "memory")
#define CP_WAIT2  asm volatile("cp.async.wait_group 2;" ::: "memory")
#define CP_WAIT1  asm volatile("cp.async.wait_group 1;" ::: "memory")
#define CP_WAIT0  asm volatile("cp.async.wait_group 0;" ::: "memory")

__device__ __forceinline__ uint32_t sw128(uint32_t off){ return off ^ ((off>>3)&0x70u); }

__device__ __forceinline__ void panel_write(__nv_bfloat16* pan, int panKc, int mglob, int cglob, float v){
    int pm = mglob>>7, prow = mglob&127, chunk = cglob>>6, col = cglob&63;
    uint32_t off = sw128((uint32_t)(prow*128 + col*2));
    char* hi = (char*)(pan + ((size_t)pm*(2*panKc)+chunk)*8192);
    char* lo = (char*)(pan + ((size_t)pm*(2*panKc)+panKc+chunk)*8192);
    __nv_bfloat16 h = __float2bfloat16(v);
    *(__nv_bfloat16*)(hi+off) = h;
    *(__nv_bfloat16*)(lo+off) = __float2bfloat16(v - __bfloat162float(h));
}

__device__ __forceinline__ void w_write(const float* __restrict__ W, __nv_bfloat16* P,
                                        int N, int KcN, int idx){
    int k = idx / N, n = idx - k*N;
    float v = W[idx];
    __nv_bfloat16 hi = __float2bfloat16(v);
    __nv_bfloat16 lo = __float2bfloat16(v - __bfloat162float(hi));
    int nblk = n>>7, row = n&127, chunk = k>>6, col = k&63;
    uint32_t off = sw128((uint32_t)(row*128 + col*2));
    char* baseHi = (char*)(P + ((size_t)nblk*(2*KcN)+chunk)*8192);
    char* baseLo = (char*)(P + ((size_t)nblk*(2*KcN)+KcN+chunk)*8192);
    *(__nv_bfloat16*)(baseHi + off) = hi;
    *(__nv_bfloat16*)(baseLo + off) = lo;
}

// ---------------- mega prologue: eemb | edge scatter | weight panels ----------------
__global__ void prologue_kernel(const float* __restrict__ sent_emb,
                                const int* __restrict__ ev_sent,
                                const int* __restrict__ ev_start,
                                const int* __restrict__ ev_end,
                                const int* __restrict__ pair_idx,
                                const int* __restrict__ rel_type,
                                const float* __restrict__ Win,
                                const float* __restrict__ W1,
                                const float* __restrict__ Wp){
    int b = blockIdx.x, tid = threadIdx.x;
    if(b < Nn){
        int n = b;
        int s = ev_sent[n], st = ev_start[n], en = ev_end[n];
        float inv = 1.0f/(float)(en-st);
        const float* base = sent_emb + (size_t)s*Ll*Ee;
        if(tid < Ee/4){
            float4 acc = make_float4(0.f,0.f,0.f,0.f);
#pragma unroll
            for(int m=0;m<Mm;m++){
                int pos = st+m;
                if(pos<en){
                    int pc = pos<Ll-1?pos:Ll-1;
                    float4 t = *(const float4*)(base + (size_t)pc*Ee + tid*4);
                    acc.x += t.x; acc.y += t.y; acc.z += t.z; acc.w += t.w;
                }
            }
            int c = tid*4;
            panel_write(g_PE, KC_E, n, c+0, acc.x*inv);
            panel_write(g_PE, KC_E, n, c+1, acc.y*inv);
            panel_write(g_PE, KC_E, n, c+2, acc.z*inv);
            panel_write(g_PE, KC_E, n, c+3, acc.w*inv);
        }
    } else if(b < Nn + NE/256){
        int e = (b - Nn)*256 + tid;
        int p = e & (Pp-1);
        int half = (e>=Pp);
        int src = half ? pair_idx[2*p+1] : pair_idx[2*p];
        int dst = half ? pair_idx[2*p]   : pair_idx[2*p+1];
        unsigned int intra = (rel_type[p]==0) ? 0x40000000u : 0u;
        int slot = atomicAdd(&g_cnt[dst],1);
        int idx = dst*DEG_CAP + slot;
        g_esrc[idx] = src;
        g_emeta[idx] = (unsigned int)p | (half ? 0x80000000u : 0u) | intra;
    } else {
        int wb = b - (Nn + NE/256);   // 0..8191
        if(wb < 768){
            w_write(Win, g_Wbig, Cc, KC_E, wb*256+tid);
        } else if(wb < 3840){
            w_write(W1, g_Wbig + (size_t)2*(2*KC_E)*8192, MLPH, KC_E, (wb-768)*256+tid);
        } else if(wb < 6912){
            w_write(W1 + (size_t)Ee*MLPH, g_Wbig + (size_t)10*(2*KC_E)*8192, MLPH, KC_E, (wb-3840)*256+tid);
        } else if(wb < 7936){
            w_write(W1 + (size_t)2*Ee*MLPH, g_Wloop, MLPH, KC_C, (wb-6912)*256+tid);
        } else {
            w_write(Wp, g_Wloop + (size_t)8*(2*KC_C)*8192, Cc, KC_C, (wb-7936)*256+tid);
        }
    }
}

// ---------------- epilogue descriptor ----------------
struct Epi {
    int type;              // 0 fp32 out(+bias); 1 UV; 2 panel out(+bias)
    float* out;
    const float* bias;
    int N;
    float* out2;
    __nv_bfloat16* pan;
    int panKc;
};

// ---------------- fused GEMM: 128x128 CTA tile, 3-stage ----------------
#define STAGE_BYTES 32768
#define GEMM_SMEM   (3*STAGE_BYTES)

__global__ void __launch_bounds__(256,2)
gemm_fused(const __nv_bfloat16* __restrict__ Apan,
           const __nv_bfloat16* __restrict__ Bpan,
           int KcN, int s1, int s2,
           Epi e0, Epi e1, Epi e2,
           const float* __restrict__ addA,
           const float* __restrict__ addB)
{
    extern __shared__ __align__(128) char smem[];
    const uint32_t sb = smem_to_u32(smem);
    const int tid = threadIdx.x;
    const int wid = tid >> 5;
    const int lane = tid & 31;
    const int mblk = blockIdx.y, nblk = blockIdx.x;
    const int wm = wid & 3;
    const int wn = wid >> 2;
    const int nc = 3*KcN;

    float acc[2][8][4];
#pragma unroll
    for(int i=0;i<2;i++)
#pragma unroll
        for(int j=0;j<8;j++)
#pragma unroll
            for(int q=0;q<4;q++) acc[i][j][q]=0.f;

    const int arow = wm*32 + (lane & 15);
    const int acol = ((lane >> 4) & 1) * 8;
    const int bnof = ((lane >> 4) & 1) * 8 + (lane & 7);
    const int bkof = ((lane >> 3) & 1) * 8;

    auto issue_chunk = [&](int c, uint32_t dst){
        int seg = (c >= 2*KcN) ? 2 : ((c >= KcN) ? 1 : 0);
        int within = c - seg*KcN;
        int aC = (seg==1 ? KcN : 0) + within;
        int bC = (seg==2 ? KcN : 0) + within;
        const uint4* Ag = (const uint4*)(Apan + ((size_t)mblk*(2*KcN)+aC)*8192);
        const uint4* Bg = (const uint4*)(Bpan + ((size_t)nblk*(2*KcN)+bC)*8192);
#pragma unroll
        for(int i=0;i<4;i++){
            CP_ASYNC16(dst + (tid + i*256)*16, Ag + tid + i*256);
            CP_ASYNC16(dst + 16384 + (tid + i*256)*16, Bg + tid + i*256);
        }
        CP_COMMIT;
    };

    issue_chunk(0, sb);
    if(nc > 1) issue_chunk(1, sb + STAGE_BYTES);

    int bufc = 0;
    for(int c=0;c<nc;c++){
        if(c+2 < nc){
            int b2 = bufc+2; if(b2>=3) b2-=3;
            issue_chunk(c+2, sb + b2*STAGE_BYTES);
            CP_WAIT2;
        } else if(c+1 < nc){
            CP_WAIT1;
        } else {
            CP_WAIT0;
        }
        __syncthreads();

        uint32_t abase = sb + bufc*STAGE_BYTES;
        uint32_t bbase = abase + 16384;
#pragma unroll
        for(int ks=0;ks<4;ks++){
            uint32_t af[2][4];
#pragma unroll
            for(int mf=0;mf<2;mf++){
                uint32_t off = (uint32_t)((arow + mf*16)*128 + (ks*16 + acol)*2);
                ldmx4(af[mf][0],af[mf][1],af[mf][2],af[mf][3], abase + sw128(off));
            }
#pragma unroll
            for(int g=0;g<4;g++){
                uint32_t b0,b1,b2,b3;
                uint32_t off = (uint32_t)((wn*64 + g*16 + bnof)*128 + (ks*16 + bkof)*2);
                ldmx4(b0,b1,b2,b3, bbase + sw128(off));
#pragma unroll
                for(int mf=0;mf<2;mf++){
                    mma16816(acc[mf][2*g+0], af[mf], b0, b1);
                    mma16816(acc[mf][2*g+1], af[mf], b2, b3);
                }
            }
        }
        __syncthreads();
        if(++bufc==3) bufc=0;
    }

    Epi E; int regStart;
    if(nblk < s1){ E = e0; regStart = 0; }
    else if(nblk < s2){ E = e1; regStart = s1; }
    else { E = e2; regStart = s2; }

    int rbase = mblk*128 + wm*32 + (lane>>2);
    int cbase = (nblk - regStart)*128 + wn*64 + (lane&3)*2;

#pragma unroll
    for(int mf=0;mf<2;mf++){
#pragma unroll
        for(int nf=0;nf<8;nf++){
            int r  = rbase + mf*16;
            int cc = cbase + nf*8;
            float g0=acc[mf][nf][0], g1=acc[mf][nf][1];
            float g2=acc[mf][nf][2], g3=acc[mf][nf][3];
            if(E.type==0){
                float b0 = E.bias ? E.bias[cc]   : 0.f;
                float b1 = E.bias ? E.bias[cc+1] : 0.f;
                size_t i0 = (size_t)r*E.N + cc;
                size_t i1 = (size_t)(r+8)*E.N + cc;
                *(float2*)(E.out + i0) = make_float2(g0+b0, g1+b1);
                *(float2*)(E.out + i1) = make_float2(g2+b0, g3+b1);
            } else if(E.type==1){
                float b0 = E.bias[cc], b1 = E.bias[cc+1];
                size_t i0 = (size_t)r*E.N + cc;
                size_t i1 = (size_t)(r+8)*E.N + cc;
                float2 a0 = *(const float2*)(addA + i0);
                float2 a1 = *(const float2*)(addA + i1);
                float2 v0 = *(const float2*)(addB + i0);
                float2 v1 = *(const float2*)(addB + i1);
                *(float2*)(E.out  + i0) = make_float2(a0.x+g0+b0, a0.y+g1+b1);
                *(float2*)(E.out  + i1) = make_float2(a1.x+g2+b0, a1.y+g3+b1);
                *(float2*)(E.out2 + i0) = make_float2(v0.x-g0, v0.y-g1);
                *(float2*)(E.out2 + i1) = make_float2(v1.x-g2, v1.y-g3);
            } else {
                float b0 = E.bias ? E.bias[cc]   : 0.f;
                float b1 = E.bias ? E.bias[cc+1] : 0.f;
                panel_write(E.pan, E.panKc, r,   cc,   g0+b0);
                panel_write(E.pan, E.panKc, r,   cc+1, g1+b1);
                panel_write(E.pan, E.panKc, r+8, cc,   g2+b0);
                panel_write(E.pan, E.panKc, r+8, cc+1, g3+b1);
            }
        }
    }
}

// ---------------- pair MLP (2 pairs/warp ILP + u/v prefetch) + s-scores ----------------
__global__ void pair_s_kernel(const int* __restrict__ pair_idx,
                              const float* __restrict__ W2, const float* __restrict__ b2,
                              const int* __restrict__ target,
                              float w_it, int accum, float* __restrict__ pred_out,
                              const float* __restrict__ asi, const float* __restrict__ adi,
                              const float* __restrict__ ase, const float* __restrict__ ade)
{
    int tid = threadIdx.x; // 256
    if(blockIdx.x < Pp/16){
        __shared__ __align__(16) float W2t[3][MLPH];
        __shared__ float b2s[3];
        for(int i=tid;i<3072;i+=256){
            float v = W2[i];
            W2t[i%3][i/3] = v;
        }
        if(tid<3) b2s[tid]=b2[tid];
        __syncthreads();
        int lane = tid & 31;
        int pa = blockIdx.x*16 + (tid>>5)*2;
        int pb = pa + 1;
        int pa0 = pair_idx[2*pa], pa1 = pair_idx[2*pa+1];
        int pb0 = pair_idx[2*pb], pb1 = pair_idx[2*pb+1];
        const float4* ura = (const float4*)(g_U + (size_t)pa0*MLPH);
        const float4* vra = (const float4*)(g_V + (size_t)pa1*MLPH);
        const float4* urb = (const float4*)(g_U + (size_t)pb0*MLPH);
        const float4* vrb = (const float4*)(g_V + (size_t)pb1*MLPH);
        const float4* w0t = (const float4*)W2t[0];
        const float4* w1t = (const float4*)W2t[1];
        const float4* w2t = (const float4*)W2t[2];
        float aa0=0.f,aa1=0.f,aa2=0.f;
        float ba0=0.f,ba1=0.f,ba2=0.f;
        // software-pipelined u/v loads: fetch k+1 before computing k
        float4 ua = ura[lane], va = vra[lane];
        float4 ub = urb[lane], vb = vrb[lane];
#pragma unroll
        for(int k=0;k<8;k++){
            float4 nua, nva, nub, nvb;
            if(k<7){
                int j4n = lane + (k+1)*32;
                nua = ura[j4n]; nva = vra[j4n];
                nub = urb[j4n]; nvb = vrb[j4n];
            }
            int j4 = lane + k*32;
            float4 w0 = w0t[j4], w1 = w1t[j4], w2 = w2t[j4];
            float ha0 = fmaxf(ua.x+va.x,0.f);
            float ha1 = fmaxf(ua.y+va.y,0.f);
            float ha2 = fmaxf(ua.z+va.z,0.f);
            float ha3 = fmaxf(ua.w+va.w,0.f);
            float hb0 = fmaxf(ub.x+vb.x,0.f);
            float hb1 = fmaxf(ub.y+vb.y,0.f);
            float hb2 = fmaxf(ub.z+vb.z,0.f);
            float hb3 = fmaxf(ub.w+vb.w,0.f);
            aa0 += ha0*w0.x + ha1*w0.y + ha2*w0.z + ha3*w0.w;
            ba0 += hb0*w0.x + hb1*w0.y + hb2*w0.z + hb3*w0.w;
            aa1 += ha0*w1.x + ha1*w1.y + ha2*w1.z + ha3*w1.w;
            ba1 += hb0*w1.x + hb1*w1.y + hb2*w1.z + hb3*w1.w;
            aa2 += ha0*w2.x + ha1*w2.y + ha2*w2.z + ha3*w2.w;
            ba2 += hb0*w2.x + hb1*w2.y + hb2*w2.z + hb3*w2.w;
            if(k<7){ ua=nua; va=nva; ub=nub; vb=nvb; }
        }
        aa0=warp_sum(aa0); aa1=warp_sum(aa1); aa2=warp_sum(aa2);
        ba0=warp_sum(ba0); ba1=warp_sum(ba1); ba2=warp_sum(ba2);
        if(lane==0){
#pragma unroll
            for(int q=0;q<2;q++){
                int p = q ? pb : pa;
                float r0 = (q?ba0:aa0)+b2s[0];
                float r1 = (q?ba1:aa1)+b2s[1];
                float r2 = (q?ba2:aa2)+b2s[2];
                float mv=r0; int arg=0;
                if(r1>mv){mv=r1;arg=1;}
                if(r2>mv){mv=r2;arg=2;}
                float e0=expf(r0-mv), e1=expf(r1-mv), e2=expf(r2-mv);
                float ssum=e0+e1+e2;
                int conf = (1.0f/ssum) > 0.5f;
                g_m1[p] = (unsigned char)(conf && (arg==1));
                g_m2[p] = (unsigned char)(conf && (arg==2));
                int t = target[p];
                float lse = mv + logf(ssum);
                float pr = (t==0)?r0:((t==1)?r1:r2);
                float prev = accum ? g_loss[p] : 0.f;
                g_loss[p] = prev + w_it*(lse - pr);
                if(pred_out){
                    pred_out[3*p+0]=r0; pred_out[3*p+1]=r1; pred_out[3*p+2]=r2;
                }
            }
        }
    } else {
        int n = (blockIdx.x - Pp/16)*2 + (tid>>7);
        int w = (tid>>5)&3, lane = tid&31;
        const float* hr = g_h + (size_t)n*Cc + w*Dd;
        float h0 = hr[lane], h1 = hr[32+lane];
        float v0 = h0*asi[w*Dd+lane] + h1*asi[w*Dd+32+lane];
        float v1 = h0*adi[w*Dd+lane] + h1*adi[w*Dd+32+lane];
        float v2 = h0*ase[w*Dd+lane] + h1*ase[w*Dd+32+lane];
        float v3 = h0*ade[w*Dd+lane] + h1*ade[w*Dd+32+lane];
        v0=warp_sum(v0); v1=warp_sum(v1); v2=warp_sum(v2); v3=warp_sum(v3);
        if(lane==0){
            g_sis[n*Hh+w]=v0; g_sid[n*Hh+w]=v1;
            g_ses[n*Hh+w]=v2; g_sed[n*Hh+w]=v3;
        }
    }
}

// ---------------- loss reduce + g_cnt re-zero ----------------
__global__ void loss_reduce(float* __restrict__ out){
    int tid = threadIdx.x;
    if(blockIdx.x == 0){
        __shared__ float sh[256];
        float s=0.f;
        for(int i=tid;i<Pp;i+=256) s+=g_loss[i];
        sh[tid]=s; __syncthreads();
        for(int o=128;o;o>>=1){
            if(tid<o) sh[tid]+=sh[tid+o];
            __syncthreads();
        }
        if(tid==0) out[0]=sh[0]/(float)Pp;
    } else {
        g_cnt[(blockIdx.x-1)*256 + tid] = 0;
    }
}

// ---------------- fused GAT attention (bucket CSR), writes x panels ----------------
__global__ void attn_kernel(){
    int n = blockIdx.x;
    int tid = threadIdx.x; // 256
    int hh = tid>>6;
    __shared__ int ssrc[64];
    __shared__ unsigned int smeta[64];
    __shared__ float exI[64][4];
    __shared__ float exE[64][4];
    __shared__ float shmaxI[4], shmaxE[4], shdenI[4], shdenE[4];
    __shared__ float wred[8][8];

    float sdI[4], sdE[4], aself[4];
#pragma unroll
    for(int h=0;h<4;h++){
        sdI[h]=g_sid[n*4+h];
        sdE[h]=g_sed[n*4+h];
        float a = g_sis[n*4+h]+sdI[h];
        aself[h] = (a>=0.f)? a : 0.2f*a;
    }

    int beg = n*DEG_CAP;
    int end = beg + g_cnt[n];

    float mI[4], mE[4];
#pragma unroll
    for(int h=0;h<4;h++){ mI[h]=fmaxf(-1e9f,aself[h]); mE[h]=-1e9f; }
    for(int e=beg+tid;e<end;e+=256){
        int src = g_esrc[e];
        unsigned int meta = g_emeta[e];
        unsigned int p = meta & 0x0FFFFFFFu;
        bool mm = (meta & 0x80000000u) ? (g_m2[p]!=0) : (g_m1[p]!=0);
        if(!mm) continue;
        if(meta & 0x40000000u){
#pragma unroll
            for(int h=0;h<4;h++){
                float a = g_sis[src*4+h]+sdI[h];
                a = (a>=0.f)? a : 0.2f*a;
                mI[h]=fmaxf(mI[h],a);
            }
        } else {
#pragma unroll
            for(int h=0;h<4;h++){
                float a = g_ses[src*4+h]+sdE[h];
                a = (a>=0.f)? a : 0.2f*a;
                mE[h]=fmaxf(mE[h],a);
            }
        }
    }
#pragma unroll
    for(int o=16;o;o>>=1){
#pragma unroll
        for(int h=0;h<4;h++){
            mI[h]=fmaxf(mI[h],__shfl_xor_sync(0xffffffffu,mI[h],o));
            mE[h]=fmaxf(mE[h],__shfl_xor_sync(0xffffffffu,mE[h],o));
        }
    }
    int wid = tid>>5, lane = tid&31;
    if(lane==0){
#pragma unroll
        for(int h=0;h<4;h++){ wred[wid][h]=mI[h]; wred[wid][4+h]=mE[h]; }
    }
    __syncthreads();
    if(tid<8){
        float m=-1e9f;
#pragma unroll
        for(int w=0;w<8;w++) m=fmaxf(m,wred[w][tid]);
        if(tid<4) shmaxI[tid]=m; else shmaxE[tid-4]=m;
    }
    __syncthreads();
    float mymaxI = shmaxI[hh];
    float mymaxE = shmaxE[hh];

    float accI=0.f, accE=0.f, dI=0.f, dE=0.f;
    for(int c0=beg;c0<end;c0+=64){
        int ne = min(64, end-c0);
        if(tid<ne){ ssrc[tid]=g_esrc[c0+tid]; smeta[tid]=g_emeta[c0+tid]; }
        __syncthreads();
        int i = tid & 63;
        if(i<ne){
            int src = ssrc[i];
            unsigned int meta = smeta[i];
            unsigned int p = meta & 0x0FFFFFFFu;
            bool mm = (meta & 0x80000000u) ? (g_m2[p]!=0) : (g_m1[p]!=0);
            float eI=0.f, eE=0.f;
            if(mm){
                if(meta & 0x40000000u){
                    float a = g_sis[src*4+hh]+sdI[hh];
                    a = (a>=0.f)? a : 0.2f*a;
                    eI = expf(a - mymaxI);
                } else {
                    float a = g_ses[src*4+hh]+sdE[hh];
                    a = (a>=0.f)? a : 0.2f*a;
                    eE = expf(a - mymaxE);
                }
            }
            exI[i][hh]=eI; exE[i][hh]=eE;
            dI += eI; dE += eE;
        }
        __syncthreads();
        for(int i2=0;i2<ne;i2++){
            float wI = exI[i2][hh];
            float wE = exE[i2][hh];
            if(wI!=0.f || wE!=0.f){
                float hv = g_h[(size_t)ssrc[i2]*Cc + tid];
                accI += wI*hv;
                accE += wE*hv;
            }
        }
        __syncthreads();
    }

    float rdI = warp_sum(dI), rdE = warp_sum(dE);
    if(lane==0){ wred[wid][0]=rdI; wred[wid][1]=rdE; }
    __syncthreads();
    if(tid<4){
        float selfe = expf(aself[tid]-shmaxI[tid]);
        shdenI[tid] = wred[2*tid][0]+wred[2*tid+1][0]+selfe;
        shdenE[tid] = wred[2*tid][1]+wred[2*tid+1][1];
    }
    __syncthreads();

    float selfe = expf(aself[hh]-mymaxI);
    accI += selfe * g_h[(size_t)n*Cc + tid];

    float outI = accI/(shdenI[hh]+1e-9f);
    float outE = accE/(shdenE[hh]+1e-9f);
    float val = 0.5f*outI + 0.5f*outE;
    panel_write(g_PX, KC_C, n, tid, val);
}

// ---------------- host launch ----------------
extern "C" void kernel_launch(void* const* d_in, const int* in_sizes, int n_in,
                              void* d_out, int out_size)
{
    const float* sent_emb  = (const float*)d_in[0];
    const float* proj_in_W = (const float*)d_in[1];
    const float* proj_in_b = (const float*)d_in[2];
    const float* proj_W    = (const float*)d_in[3];
    const float* proj_b    = (const float*)d_in[4];
    const float* asi       = (const float*)d_in[5];
    const float* adi       = (const float*)d_in[6];
    const float* ase       = (const float*)d_in[7];
    const float* ade       = (const float*)d_in[8];
    const float* mlp_W1    = (const float*)d_in[9];
    const float* mlp_b1    = (const float*)d_in[10];
    const float* mlp_W2    = (const float*)d_in[11];
    const float* mlp_b2    = (const float*)d_in[12];
    const int*   ev_sent   = (const int*)d_in[13];
    const int*   ev_start  = (const int*)d_in[14];
    const int*   ev_end    = (const int*)d_in[15];
    const int*   pair_idx  = (const int*)d_in[16];
    const int*   rel_type  = (const int*)d_in[17];
    const int*   target    = (const int*)d_in[18];
    float* out = (float*)d_out;

    static float *pA=nullptr,*pB=nullptr,*pU=nullptr,*pV=nullptr,*pH=nullptr;
    static __nv_bfloat16 *qE,*qX,*qWbig,*qWloop;
    if(!pA){
        cudaGetSymbolAddress((void**)&pA, g_A);
        cudaGetSymbolAddress((void**)&pB, g_B);
        cudaGetSymbolAddress((void**)&pU, g_U);
        cudaGetSymbolAddress((void**)&pV, g_V);
        cudaGetSymbolAddress((void**)&pH, g_h);
        cudaGetSymbolAddress((void**)&qE,    g_PE);
        cudaGetSymbolAddress((void**)&qX,    g_PX);
        cudaGetSymbolAddress((void**)&qWbig, g_Wbig);
        cudaGetSymbolAddress((void**)&qWloop,g_Wloop);
        cudaFuncSetAttribute(gemm_fused, cudaFuncAttributeMaxDynamicSharedMemorySize, GEMM_SMEM);
    }

    // single prologue launch: eemb | scatter | weight panels
    prologue_kernel<<<Nn + NE/256 + 8192, 256>>>(sent_emb, ev_sent, ev_start, ev_end,
                                                 pair_idx, rel_type,
                                                 proj_in_W, mlp_W1, proj_W);

    // fused big GEMM: [x-panels(2 tiles) | A(8) | B(8)] = e_emb @ [Win | W1a | W1b]
    {
        Epi ex;  ex.type=2;  ex.out=nullptr; ex.bias=proj_in_b; ex.N=0;    ex.out2=nullptr; ex.pan=qX; ex.panKc=KC_C;
        Epi ea;  ea.type=0;  ea.out=pA;      ea.bias=nullptr;   ea.N=MLPH; ea.out2=nullptr; ea.pan=nullptr; ea.panKc=0;
        Epi eb;  eb.type=0;  eb.out=pB;      eb.bias=nullptr;   eb.N=MLPH; eb.out2=nullptr; eb.pan=nullptr; eb.panKc=0;
        gemm_fused<<<dim3(18, Nn/128),256,GEMM_SMEM>>>(qE, qWbig, KC_E, 2, 10, ex, ea, eb, nullptr, nullptr);
    }

    for(int it=0; it<3; it++){
        Epi eu;  eu.type=1;  eu.out=pU;  eu.bias=mlp_b1; eu.N=MLPH; eu.out2=pV;      eu.pan=nullptr; eu.panKc=0;
        Epi eh;  eh.type=0;  eh.out=pH;  eh.bias=proj_b; eh.N=Cc;   eh.out2=nullptr; eh.pan=nullptr; eh.panKc=0;
        int gx = (it<2) ? 10 : 8;
        gemm_fused<<<dim3(gx, Nn/128),256,GEMM_SMEM>>>(qX, qWloop, KC_C, 8, 10, eu, eh, eh, pA, pB);

        int sgrid = (it<2) ? (Pp/16 + Nn/2) : (Pp/16);
        pair_s_kernel<<<sgrid,256>>>(pair_idx, mlp_W2, mlp_b2, target,
                                     1.0f/(float)(it+1), it>0,
                                     (it==2) ? (out+1) : nullptr,
                                     asi, adi, ase, ade);
        if(it<2){
            attn_kernel<<<Nn,256>>>();
        }
    }
    loss_reduce<<<1 + Nn/256,256>>>(out);
}